// round 2
// baseline (speedup 1.0000x reference)
#include <cuda_runtime.h>
#include <cuda_bf16.h>

// GenderAwareCrossEntropyLoss: per-row CE(log_softmax, label) * weight +
// 5.0 penalty when argmax class is invalid for (g1,g2); mean over N rows.
//
// HBM-bound streaming reduction, single fused kernel.
// Each thread owns 4 consecutive rows -> 7 aligned float4 loads (112B) per
// thread for logits; reduction fused via last-block pattern (deterministic:
// one block reduces partials in fixed order, double precision).

#define ROWS_PER_THREAD 4
#define BLOCK_THREADS   256
#define MAX_BLOCKS      16384

__device__ float        g_partials[MAX_BLOCKS];
__device__ unsigned int g_count = 0;   // zero-init; returns to 0 every launch

// VALID table packed: for g = g1*2+g2, valid-class bitmask (7 bits each):
//  g=0 (0,0): {1,4}   -> 0b0010010 = 18
//  g=1 (0,1): {0,3,6} -> 0b1001001 = 73
//  g=2 (1,0): {0,3,6} -> 73
//  g=3 (1,1): {2,5}   -> 0b0100100 = 36
#define VALID_PACKED ((18u) | (73u << 7) | (73u << 14) | (36u << 21))

__global__ __launch_bounds__(BLOCK_THREADS)
void gace_fused_kernel(const float* __restrict__ logits,
                       const float* __restrict__ class_weights,
                       const int*   __restrict__ labels,
                       const int*   __restrict__ gender,
                       float*       __restrict__ out,
                       int nrows, int ngroups)
{
    float cw[7];
#pragma unroll
    for (int c = 0; c < 7; c++) cw[c] = __ldg(&class_weights[c]);

    float acc = 0.0f;

    int grp = blockIdx.x * BLOCK_THREADS + threadIdx.x;
    if (grp < ngroups) {
        int r0 = grp * ROWS_PER_THREAD;

        if (r0 + ROWS_PER_THREAD <= nrows) {
            // ---- front-batched wide streaming loads (max MLP, evict-first) ----
            float4 lv[7];
            const float4* lp = reinterpret_cast<const float4*>(logits + (size_t)r0 * 7);
#pragma unroll
            for (int i = 0; i < 7; i++) lv[i] = __ldcs(&lp[i]);

            int4 lab4 = __ldcs(reinterpret_cast<const int4*>(labels + r0));
            const int4* gp = reinterpret_cast<const int4*>(gender + (size_t)r0 * 2);
            int4 gA = __ldcs(&gp[0]);
            int4 gB = __ldcs(&gp[1]);

            const float* x = reinterpret_cast<const float*>(lv);
            int labs[4] = { lab4.x, lab4.y, lab4.z, lab4.w };
            int gidx[4] = { gA.x * 2 + gA.y, gA.z * 2 + gA.w,
                            gB.x * 2 + gB.y, gB.z * 2 + gB.w };

#pragma unroll
            for (int j = 0; j < 4; j++) {
                float v0 = x[j*7+0], v1 = x[j*7+1], v2 = x[j*7+2], v3 = x[j*7+3];
                float v4 = x[j*7+4], v5 = x[j*7+5], v6 = x[j*7+6];

                // argmax (first max wins, matching jnp.argmax) + row max
                float m = v0; int am = 0;
                if (v1 > m) { m = v1; am = 1; }
                if (v2 > m) { m = v2; am = 2; }
                if (v3 > m) { m = v3; am = 3; }
                if (v4 > m) { m = v4; am = 4; }
                if (v5 > m) { m = v5; am = 5; }
                if (v6 > m) { m = v6; am = 6; }

                float s = __expf(v0 - m) + __expf(v1 - m) + __expf(v2 - m)
                        + __expf(v3 - m) + __expf(v4 - m) + __expf(v5 - m)
                        + __expf(v6 - m);

                // gather x[label] / weight[label] via select chain (no spills)
                int lab = labs[j];
                float xl = v0;
                xl = (lab == 1) ? v1 : xl;
                xl = (lab == 2) ? v2 : xl;
                xl = (lab == 3) ? v3 : xl;
                xl = (lab == 4) ? v4 : xl;
                xl = (lab == 5) ? v5 : xl;
                xl = (lab == 6) ? v6 : xl;

                float w = cw[0];
                w = (lab == 1) ? cw[1] : w;
                w = (lab == 2) ? cw[2] : w;
                w = (lab == 3) ? cw[3] : w;
                w = (lab == 4) ? cw[4] : w;
                w = (lab == 5) ? cw[5] : w;
                w = (lab == 6) ? cw[6] : w;

                float ce = __logf(s) - (xl - m);   // -logp[label]

                unsigned bit = (VALID_PACKED >> (gidx[j] * 7 + am)) & 1u;
                float pen = bit ? 0.0f : 5.0f;

                acc += w * ce + pen;
            }
        } else {
            for (int r = r0; r < nrows; r++) {
                float v[7];
#pragma unroll
                for (int c = 0; c < 7; c++) v[c] = logits[(size_t)r * 7 + c];
                float m = v[0]; int am = 0;
#pragma unroll
                for (int c = 1; c < 7; c++) if (v[c] > m) { m = v[c]; am = c; }
                float s = 0.0f;
#pragma unroll
                for (int c = 0; c < 7; c++) s += __expf(v[c] - m);
                int lab = labels[r];
                float xl = v[0], w = cw[0];
#pragma unroll
                for (int c = 1; c < 7; c++) {
                    xl = (lab == c) ? v[c] : xl;
                    w  = (lab == c) ? cw[c] : w;
                }
                int g = gender[(size_t)r * 2] * 2 + gender[(size_t)r * 2 + 1];
                unsigned bit = (VALID_PACKED >> (g * 7 + am)) & 1u;
                acc += w * (__logf(s) - (xl - m)) + (bit ? 0.0f : 5.0f);
            }
        }
    }

    // ---- deterministic block reduction (float within block) ----
    __shared__ float wsum[BLOCK_THREADS / 32];
    __shared__ bool  s_isLast;
    int lane = threadIdx.x & 31;
    int wid  = threadIdx.x >> 5;
#pragma unroll
    for (int o = 16; o > 0; o >>= 1)
        acc += __shfl_down_sync(0xffffffffu, acc, o);
    if (lane == 0) wsum[wid] = acc;
    __syncthreads();
    if (threadIdx.x == 0) {
        float bsum = 0.0f;
#pragma unroll
        for (int i = 0; i < BLOCK_THREADS / 32; i++) bsum += wsum[i];
        g_partials[blockIdx.x] = bsum;
        __threadfence();
        unsigned old = atomicAdd(&g_count, 1u);
        s_isLast = (old == gridDim.x - 1);
    }
    __syncthreads();

    // ---- last block: deterministic final reduce in double ----
    if (s_isLast) {
        __shared__ double dsm[BLOCK_THREADS];
        double s = 0.0;
        for (int i = threadIdx.x; i < (int)gridDim.x; i += BLOCK_THREADS)
            s += (double)g_partials[i];
        dsm[threadIdx.x] = s;
        __syncthreads();
#pragma unroll
        for (int st = BLOCK_THREADS / 2; st > 0; st >>= 1) {
            if (threadIdx.x < st) dsm[threadIdx.x] += dsm[threadIdx.x + st];
            __syncthreads();
        }
        if (threadIdx.x == 0) {
            out[0] = (float)(dsm[0] / (double)nrows);
            g_count = 0;   // reset for next graph replay
        }
    }
}

extern "C" void kernel_launch(void* const* d_in, const int* in_sizes, int n_in,
                              void* d_out, int out_size)
{
    const float* logits        = (const float*)d_in[0];
    const float* class_weights = (const float*)d_in[1];
    const int*   labels        = (const int*)d_in[2];
    const int*   gender        = (const int*)d_in[3];
    float*       out           = (float*)d_out;

    int nrows   = in_sizes[2];                       // N
    int ngroups = (nrows + ROWS_PER_THREAD - 1) / ROWS_PER_THREAD;
    int blocks  = (ngroups + BLOCK_THREADS - 1) / BLOCK_THREADS;
    if (blocks > MAX_BLOCKS) blocks = MAX_BLOCKS;    // N=4M -> 3907 blocks, no cap

    gace_fused_kernel<<<blocks, BLOCK_THREADS>>>(logits, class_weights, labels,
                                                 gender, out, nrows, ngroups);
}